// round 12
// baseline (speedup 1.0000x reference)
#include <cuda_runtime.h>
#include <cuda_bf16.h>
#include <math.h>

#define BS   8
#define SEQ  512
#define C    512
#define NC   5
#define H    768
#define W    768
#define HW   (H*W)
#define NTOK (BS*SEQ)          // 4096

#define THREADS 256
#define NWARP   (THREADS/32)
#define GRID    NTOK           // one block per token

// Scratch (no allocations allowed)
__device__ float g_nll[NTOK];
__device__ int   g_msk[NTOK];
__device__ int   g_ctr;        // zero-init; reset at end of each run

// ---------------------------------------------------------------------------
// ONE kernel, BLOCK per token (32K warps total -> full occupancy, multi-wave):
//   - mask==0 tokens: record m=0, skip GEMV + box scan entirely (~2x work cut)
//   - logits: 256-thread GEMV, Wc via __ldg (10KB, L1/L2-hot), fixed-order
//     combine (warp shfl -> per-warp smem -> thread 0) = deterministic
//   - box scan: on-the-fly 5-channel argmax; mean box = ONE trip per thread
//   - first-max tiebreaks identical to jnp.argmax / bincount().argmax()
//   - last block does the deterministic fixed-order final reduction
// ---------------------------------------------------------------------------
__global__ __launch_bounds__(THREADS)
void token_kernel(const float* __restrict__ cl,
                  const float* __restrict__ fuse,
                  const float* __restrict__ Wc,
                  const float* __restrict__ bc,
                  const int*   __restrict__ coords,
                  const int*   __restrict__ mask,
                  float* __restrict__ out) {
    __shared__ float sA[NWARP][NC];   // per-warp GEMV partials
    __shared__ int   sC[NWARP][NC];   // per-warp count partials

    const int t    = blockIdx.x;
    const int tid  = threadIdx.x;
    const int warp = tid >> 5;
    const int lane = tid & 31;
    const int b    = t / SEQ;

    const int m = mask[t];
    if (m == 1) {
        // ---- logits GEMV: thread k covers columns k and k+256 ----
        const float* fe = fuse + (size_t)t * C;
        float e0 = fe[tid];
        float e1 = fe[tid + 256];
        float a[NC];
#pragma unroll
        for (int c = 0; c < NC; ++c) {
            a[c] = e0 * __ldg(Wc + c*C + tid)
                 + e1 * __ldg(Wc + c*C + tid + 256);
        }
#pragma unroll
        for (int off = 16; off; off >>= 1) {
#pragma unroll
            for (int c = 0; c < NC; ++c)
                a[c] += __shfl_xor_sync(0xffffffffu, a[c], off);
        }
        if (lane == 0) {
#pragma unroll
            for (int c = 0; c < NC; ++c) sA[warp][c] = a[c];
        }

        // ---- box scan: 256 threads, on-the-fly per-pixel argmax ----
        int x0 = coords[t*4+0], y0 = coords[t*4+1];
        int x1 = coords[t*4+2], y1 = coords[t*4+3];
        if (y1 == y0) y1 = y0 + 1;
        if (x1 == x0) x1 = x0 + 1;

        const int wpx  = x1 - x0;
        const int rows = y1 - y0;
        const int nidx = rows * wpx;

        const float* clb = cl + (size_t)b * NC * HW;
        int cnt[NC] = {0, 0, 0, 0, 0};
        for (int idx = tid; idx < nidx; idx += THREADS) {
            int ry = idx / wpx;
            int x  = x0 + (idx - ry * wpx);
            size_t p = (size_t)(y0 + ry) * W + x;
            float v0 = __ldg(clb + p);
            float v1 = __ldg(clb + p + 1*(size_t)HW);
            float v2 = __ldg(clb + p + 2*(size_t)HW);
            float v3 = __ldg(clb + p + 3*(size_t)HW);
            float v4 = __ldg(clb + p + 4*(size_t)HW);
            float best = v0; int lab = 0;
            if (v1 > best) { best = v1; lab = 1; }
            if (v2 > best) { best = v2; lab = 2; }
            if (v3 > best) { best = v3; lab = 3; }
            if (v4 > best) { best = v4; lab = 4; }
            ++cnt[lab];
        }
#pragma unroll
        for (int c = 0; c < NC; ++c)
            cnt[c] = __reduce_add_sync(0xffffffffu, cnt[c]);
        if (lane == 0) {
#pragma unroll
            for (int c = 0; c < NC; ++c) sC[warp][c] = cnt[c];
        }
        __syncthreads();

        // ---- finalize: thread 0, fixed combine order (deterministic) ----
        if (tid == 0) {
            int   cc[NC];
            float lg[NC];
#pragma unroll
            for (int c = 0; c < NC; ++c) { cc[c] = 0; lg[c] = 0.f; }
#pragma unroll
            for (int w = 0; w < NWARP; ++w) {
#pragma unroll
                for (int c = 0; c < NC; ++c) {
                    cc[c] += sC[w][c];
                    lg[c] += sA[w][c];
                }
            }
            int maj = 0, bestc = cc[0];
#pragma unroll
            for (int c = 1; c < NC; ++c)
                if (cc[c] > bestc) { bestc = cc[c]; maj = c; }

#pragma unroll
            for (int c = 0; c < NC; ++c) lg[c] += bc[c];
            float mx = lg[0];
#pragma unroll
            for (int c = 1; c < NC; ++c) mx = fmaxf(mx, lg[c]);
            float se = 0.f;
#pragma unroll
            for (int c = 0; c < NC; ++c) se += expf(lg[c] - mx);
            float nll = -(lg[maj] - mx - logf(se));

            g_nll[t] = nll;
            g_msk[t] = 1;
        }
    } else {
        if (tid == 0) { g_nll[t] = 0.f; g_msk[t] = 0; }
    }

    // ---- last-block-done deterministic reduction ----
    __shared__ bool s_last;
    __threadfence();
    __syncthreads();
    if (tid == 0) {
        s_last = (atomicAdd(&g_ctr, 1) == GRID - 1);
    }
    __syncthreads();
    if (!s_last) return;
    __threadfence();

    __shared__ float sf[THREADS];
    __shared__ int   si[THREADS];
    float a = 0.f; int mm = 0;
#pragma unroll
    for (int i = tid; i < NTOK; i += THREADS) {
        a += g_nll[i]; mm += g_msk[i];
    }
    sf[tid] = a; si[tid] = mm;
    __syncthreads();
#pragma unroll
    for (int s = THREADS/2; s > 0; s >>= 1) {
        if (tid < s) { sf[tid] += sf[tid+s]; si[tid] += si[tid+s]; }
        __syncthreads();
    }
    if (tid == 0) {
        out[0] = sf[0] / (float)si[0];
        g_ctr = 0;                 // reset for next graph replay
    }
}

extern "C" void kernel_launch(void* const* d_in, const int* in_sizes, int n_in,
                              void* d_out, int out_size) {
    const float* fuse   = (const float*)d_in[0];   // [8,512,512]
    const float* cl     = (const float*)d_in[1];   // [8,5,768,768]
    const float* Wc     = (const float*)d_in[2];   // [5,512]
    const float* bc     = (const float*)d_in[3];   // [5]
    const int*   coords = (const int*)d_in[4];     // [8,512,4]
    const int*   mask   = (const int*)d_in[5];     // [8,512]
    float* out = (float*)d_out;

    token_kernel<<<GRID, THREADS>>>(cl, fuse, Wc, bc, coords, mask, out);
}

// round 14
// speedup vs baseline: 1.2388x; 1.2388x over previous
#include <cuda_runtime.h>
#include <cuda_bf16.h>
#include <math.h>

#define BS   8
#define SEQ  512
#define C    512
#define NC   5
#define H    768
#define W    768
#define HW   (H*W)
#define NTOK (BS*SEQ)          // 4096

#define THREADS 256
#define GRID    (NTOK / 8)     // 512 blocks, 8 warps = 8 tokens each

// Scratch (no allocations allowed)
__device__ float g_nll[NTOK];
__device__ int   g_msk[NTOK];
__device__ int   g_ctr;        // zero-init; reset at end of each run

// ---------------------------------------------------------------------------
// ONE kernel, one warp per token (R8 structure — best measured shape):
//   - NEW: mask!=1 tokens (~50%) skip GEMV + box scan entirely; the
//     reference's masked mean never reads their nll.
//   - logits[5] via warp GEMV (Wc staged in shared)
//   - box scan directly over class_labels: per-pixel 5-channel argmax on the
//     fly (first-max tiebreak, same as jnp.argmax), per-class counts in regs
//   - majority vote (first-max, matches bincount().argmax()), NLL
//   - last block does the deterministic fixed-order final reduction
// ---------------------------------------------------------------------------
__global__ __launch_bounds__(THREADS)
void token_kernel(const float* __restrict__ cl,
                  const float* __restrict__ fuse,
                  const float* __restrict__ Wc,
                  const float* __restrict__ bc,
                  const int*   __restrict__ coords,
                  const int*   __restrict__ mask,
                  float* __restrict__ out) {
    __shared__ float sW[NC * C];                 // 10 KB
    for (int i = threadIdx.x; i < NC * C; i += THREADS)
        sW[i] = Wc[i];
    __syncthreads();

    const int warp = threadIdx.x >> 5;
    const int lane = threadIdx.x & 31;
    const int t = blockIdx.x * 8 + warp;         // token id
    const int b = t / SEQ;

    const int m = mask[t];
    if (m == 1) {
        // ---- logits (warp GEMV, float4) ----
        const float4* fe4 = reinterpret_cast<const float4*>(fuse + (size_t)t * C);
        const float4* sW4 = reinterpret_cast<const float4*>(sW);
        float acc0=0.f, acc1=0.f, acc2=0.f, acc3=0.f, acc4=0.f;
#pragma unroll
        for (int i = lane; i < C/4; i += 32) {
            float4 e  = fe4[i];
            float4 w0 = sW4[0*(C/4) + i];
            float4 w1 = sW4[1*(C/4) + i];
            float4 w2 = sW4[2*(C/4) + i];
            float4 w3 = sW4[3*(C/4) + i];
            float4 w4 = sW4[4*(C/4) + i];
            acc0 += e.x*w0.x + e.y*w0.y + e.z*w0.z + e.w*w0.w;
            acc1 += e.x*w1.x + e.y*w1.y + e.z*w1.z + e.w*w1.w;
            acc2 += e.x*w2.x + e.y*w2.y + e.z*w2.z + e.w*w2.w;
            acc3 += e.x*w3.x + e.y*w3.y + e.z*w3.z + e.w*w3.w;
            acc4 += e.x*w4.x + e.y*w4.y + e.z*w4.z + e.w*w4.w;
        }
#pragma unroll
        for (int off = 16; off; off >>= 1) {
            acc0 += __shfl_xor_sync(0xffffffffu, acc0, off);
            acc1 += __shfl_xor_sync(0xffffffffu, acc1, off);
            acc2 += __shfl_xor_sync(0xffffffffu, acc2, off);
            acc3 += __shfl_xor_sync(0xffffffffu, acc3, off);
            acc4 += __shfl_xor_sync(0xffffffffu, acc4, off);
        }

        // ---- box scan: on-the-fly per-pixel argmax + counting ----
        int x0 = coords[t*4+0], y0 = coords[t*4+1];
        int x1 = coords[t*4+2], y1 = coords[t*4+3];
        if (y1 == y0) y1 = y0 + 1;
        if (x1 == x0) x1 = x0 + 1;

        const int wpx  = x1 - x0;                // box width (<=64ish)
        const int rows = y1 - y0;
        const int nidx = rows * wpx;             // flattened pixel space

        const float* clb = cl + (size_t)b * NC * HW;
        int c0=0, c1=0, c2=0, c3=0, c4=0;
        for (int idx = lane; idx < nidx; idx += 32) {
            int ry = idx / wpx;
            int x  = x0 + (idx - ry * wpx);
            size_t p = (size_t)(y0 + ry) * W + x;
            float v0 = __ldg(clb + p);
            float v1 = __ldg(clb + p + 1*(size_t)HW);
            float v2 = __ldg(clb + p + 2*(size_t)HW);
            float v3 = __ldg(clb + p + 3*(size_t)HW);
            float v4 = __ldg(clb + p + 4*(size_t)HW);
            float best = v0; int lab = 0;
            if (v1 > best) { best = v1; lab = 1; }
            if (v2 > best) { best = v2; lab = 2; }
            if (v3 > best) { best = v3; lab = 3; }
            if (v4 > best) { best = v4; lab = 4; }
            c0 += (lab==0); c1 += (lab==1); c2 += (lab==2);
            c3 += (lab==3); c4 += (lab==4);
        }
        c0 = __reduce_add_sync(0xffffffffu, c0);
        c1 = __reduce_add_sync(0xffffffffu, c1);
        c2 = __reduce_add_sync(0xffffffffu, c2);
        c3 = __reduce_add_sync(0xffffffffu, c3);
        c4 = __reduce_add_sync(0xffffffffu, c4);

        if (lane == 0) {
            int maj = 0, bestc = c0;
            if (c1 > bestc) { bestc = c1; maj = 1; }
            if (c2 > bestc) { bestc = c2; maj = 2; }
            if (c3 > bestc) { bestc = c3; maj = 3; }
            if (c4 > bestc) { bestc = c4; maj = 4; }

            float lg[NC];
            lg[0] = acc0 + bc[0]; lg[1] = acc1 + bc[1]; lg[2] = acc2 + bc[2];
            lg[3] = acc3 + bc[3]; lg[4] = acc4 + bc[4];
            float mx = lg[0];
#pragma unroll
            for (int c = 1; c < NC; ++c) mx = fmaxf(mx, lg[c]);
            float se = 0.f;
#pragma unroll
            for (int c = 0; c < NC; ++c) se += expf(lg[c] - mx);
            float nll = -(lg[maj] - mx - logf(se));

            g_nll[t] = nll;
            g_msk[t] = 1;
        }
    } else {
        // masked out: contributes 0 to numerator, 0 to denominator
        if (lane == 0) { g_nll[t] = 0.f; g_msk[t] = 0; }
    }

    // ---- last-block-done deterministic reduction ----
    __shared__ bool s_last;
    __threadfence();
    __syncthreads();
    if (threadIdx.x == 0) {
        s_last = (atomicAdd(&g_ctr, 1) == GRID - 1);
    }
    __syncthreads();
    if (!s_last) return;
    __threadfence();

    __shared__ float sf[THREADS];
    __shared__ int   si[THREADS];
    float a = 0.f; int mm = 0;
#pragma unroll
    for (int i = threadIdx.x; i < NTOK; i += THREADS) {
        a += g_nll[i]; mm += g_msk[i];
    }
    sf[threadIdx.x] = a; si[threadIdx.x] = mm;
    __syncthreads();
#pragma unroll
    for (int s = THREADS/2; s > 0; s >>= 1) {
        if (threadIdx.x < s) { sf[threadIdx.x] += sf[threadIdx.x+s];
                               si[threadIdx.x] += si[threadIdx.x+s]; }
        __syncthreads();
    }
    if (threadIdx.x == 0) {
        out[0] = sf[0] / (float)si[0];
        g_ctr = 0;                 // reset for next graph replay
    }
}

extern "C" void kernel_launch(void* const* d_in, const int* in_sizes, int n_in,
                              void* d_out, int out_size) {
    const float* fuse   = (const float*)d_in[0];   // [8,512,512]
    const float* cl     = (const float*)d_in[1];   // [8,5,768,768]
    const float* Wc     = (const float*)d_in[2];   // [5,512]
    const float* bc     = (const float*)d_in[3];   // [5]
    const int*   coords = (const int*)d_in[4];     // [8,512,4]
    const int*   mask   = (const int*)d_in[5];     // [8,512]
    float* out = (float*)d_out;

    token_kernel<<<GRID, THREADS>>>(cl, fuse, Wc, bc, coords, mask, out);
}

// round 15
// speedup vs baseline: 1.2600x; 1.0171x over previous
#include <cuda_runtime.h>
#include <cuda_bf16.h>
#include <math.h>

#define BS   8
#define SEQ  512
#define C    512
#define NC   5
#define H    768
#define W    768
#define HW   (H*W)
#define NTOK (BS*SEQ)          // 4096

#define THREADS 256
#define GRID    (NTOK / 8)     // 512 blocks, 8 warps = 8 tokens each

// Scratch (no allocations allowed)
__device__ float g_nll[NTOK];
__device__ int   g_msk[NTOK];
__device__ int   g_ctr;        // zero-init; reset at end of each run

// ---------------------------------------------------------------------------
// ONE kernel, one warp per token (best measured shape):
//   - mask!=1 tokens (~50%) skip GEMV + box scan entirely      [R14, +2us]
//   - box scan UNROLLED x4 in-warp: up to 20 independent DRAM loads
//     in flight per lane-trip -> ~2.5KB/warp in flight          [R10, MLP]
//   - logits[5] via warp GEMV (Wc staged in shared)
//   - first-max tiebreaks identical to jnp.argmax / bincount().argmax()
//   - last block does the deterministic fixed-order final reduction
// ---------------------------------------------------------------------------
__global__ __launch_bounds__(THREADS)
void token_kernel(const float* __restrict__ cl,
                  const float* __restrict__ fuse,
                  const float* __restrict__ Wc,
                  const float* __restrict__ bc,
                  const int*   __restrict__ coords,
                  const int*   __restrict__ mask,
                  float* __restrict__ out) {
    __shared__ float sW[NC * C];                 // 10 KB
    for (int i = threadIdx.x; i < NC * C; i += THREADS)
        sW[i] = Wc[i];
    __syncthreads();

    const int warp = threadIdx.x >> 5;
    const int lane = threadIdx.x & 31;
    const int t = blockIdx.x * 8 + warp;         // token id
    const int b = t / SEQ;

    const int m = mask[t];
    if (m == 1) {
        // ---- logits (warp GEMV, float4) ----
        const float4* fe4 = reinterpret_cast<const float4*>(fuse + (size_t)t * C);
        const float4* sW4 = reinterpret_cast<const float4*>(sW);
        float acc0=0.f, acc1=0.f, acc2=0.f, acc3=0.f, acc4=0.f;
#pragma unroll
        for (int i = lane; i < C/4; i += 32) {
            float4 e  = fe4[i];
            float4 w0 = sW4[0*(C/4) + i];
            float4 w1 = sW4[1*(C/4) + i];
            float4 w2 = sW4[2*(C/4) + i];
            float4 w3 = sW4[3*(C/4) + i];
            float4 w4 = sW4[4*(C/4) + i];
            acc0 += e.x*w0.x + e.y*w0.y + e.z*w0.z + e.w*w0.w;
            acc1 += e.x*w1.x + e.y*w1.y + e.z*w1.z + e.w*w1.w;
            acc2 += e.x*w2.x + e.y*w2.y + e.z*w2.z + e.w*w2.w;
            acc3 += e.x*w3.x + e.y*w3.y + e.z*w3.z + e.w*w3.w;
            acc4 += e.x*w4.x + e.y*w4.y + e.z*w4.z + e.w*w4.w;
        }
#pragma unroll
        for (int off = 16; off; off >>= 1) {
            acc0 += __shfl_xor_sync(0xffffffffu, acc0, off);
            acc1 += __shfl_xor_sync(0xffffffffu, acc1, off);
            acc2 += __shfl_xor_sync(0xffffffffu, acc2, off);
            acc3 += __shfl_xor_sync(0xffffffffu, acc3, off);
            acc4 += __shfl_xor_sync(0xffffffffu, acc4, off);
        }

        // ---- box scan: on-the-fly per-pixel argmax, x4 unroll for MLP ----
        const int4 cbox = *reinterpret_cast<const int4*>(coords + t*4);
        int x0 = cbox.x, y0 = cbox.y, x1 = cbox.z, y1 = cbox.w;
        if (y1 == y0) y1 = y0 + 1;
        if (x1 == x0) x1 = x0 + 1;

        const int wpx  = x1 - x0;                // box width (<=64ish)
        const int rows = y1 - y0;
        const int nidx = rows * wpx;             // flattened pixel space

        const float* clb = cl + (size_t)b * NC * HW;
        int c0=0, c1=0, c2=0, c3=0, c4=0;
        for (int idx = lane; idx < nidx; idx += 128) {
            float v[4][NC];
            bool  ok[4];
#pragma unroll
            for (int u = 0; u < 4; ++u) {
                int id = idx + u * 32;
                ok[u] = (id < nidx);
                if (ok[u]) {
                    int ry = id / wpx;
                    int x  = x0 + (id - ry * wpx);
                    size_t p = (size_t)(y0 + ry) * W + x;
                    v[u][0] = __ldg(clb + p);
                    v[u][1] = __ldg(clb + p + 1*(size_t)HW);
                    v[u][2] = __ldg(clb + p + 2*(size_t)HW);
                    v[u][3] = __ldg(clb + p + 3*(size_t)HW);
                    v[u][4] = __ldg(clb + p + 4*(size_t)HW);
                }
            }
#pragma unroll
            for (int u = 0; u < 4; ++u) {
                if (ok[u]) {
                    float best = v[u][0]; int lab = 0;
                    if (v[u][1] > best) { best = v[u][1]; lab = 1; }
                    if (v[u][2] > best) { best = v[u][2]; lab = 2; }
                    if (v[u][3] > best) { best = v[u][3]; lab = 3; }
                    if (v[u][4] > best) { best = v[u][4]; lab = 4; }
                    c0 += (lab==0); c1 += (lab==1); c2 += (lab==2);
                    c3 += (lab==3); c4 += (lab==4);
                }
            }
        }
        c0 = __reduce_add_sync(0xffffffffu, c0);
        c1 = __reduce_add_sync(0xffffffffu, c1);
        c2 = __reduce_add_sync(0xffffffffu, c2);
        c3 = __reduce_add_sync(0xffffffffu, c3);
        c4 = __reduce_add_sync(0xffffffffu, c4);

        if (lane == 0) {
            int maj = 0, bestc = c0;
            if (c1 > bestc) { bestc = c1; maj = 1; }
            if (c2 > bestc) { bestc = c2; maj = 2; }
            if (c3 > bestc) { bestc = c3; maj = 3; }
            if (c4 > bestc) { bestc = c4; maj = 4; }

            float lg[NC];
            lg[0] = acc0 + bc[0]; lg[1] = acc1 + bc[1]; lg[2] = acc2 + bc[2];
            lg[3] = acc3 + bc[3]; lg[4] = acc4 + bc[4];
            float mx = lg[0];
#pragma unroll
            for (int c = 1; c < NC; ++c) mx = fmaxf(mx, lg[c]);
            float se = 0.f;
#pragma unroll
            for (int c = 0; c < NC; ++c) se += expf(lg[c] - mx);
            float nll = -(lg[maj] - mx - logf(se));

            g_nll[t] = nll;
            g_msk[t] = 1;
        }
    } else {
        // masked out: contributes 0 to numerator, 0 to denominator
        if (lane == 0) { g_nll[t] = 0.f; g_msk[t] = 0; }
    }

    // ---- last-block-done deterministic reduction ----
    __shared__ bool s_last;
    __threadfence();
    __syncthreads();
    if (threadIdx.x == 0) {
        s_last = (atomicAdd(&g_ctr, 1) == GRID - 1);
    }
    __syncthreads();
    if (!s_last) return;
    __threadfence();

    __shared__ float sf[THREADS];
    __shared__ int   si[THREADS];
    float a = 0.f; int mm = 0;
#pragma unroll
    for (int i = threadIdx.x; i < NTOK; i += THREADS) {
        a += g_nll[i]; mm += g_msk[i];
    }
    sf[threadIdx.x] = a; si[threadIdx.x] = mm;
    __syncthreads();
#pragma unroll
    for (int s = THREADS/2; s > 0; s >>= 1) {
        if (threadIdx.x < s) { sf[threadIdx.x] += sf[threadIdx.x+s];
                               si[threadIdx.x] += si[threadIdx.x+s]; }
        __syncthreads();
    }
    if (threadIdx.x == 0) {
        out[0] = sf[0] / (float)si[0];
        g_ctr = 0;                 // reset for next graph replay
    }
}

extern "C" void kernel_launch(void* const* d_in, const int* in_sizes, int n_in,
                              void* d_out, int out_size) {
    const float* fuse   = (const float*)d_in[0];   // [8,512,512]
    const float* cl     = (const float*)d_in[1];   // [8,5,768,768]
    const float* Wc     = (const float*)d_in[2];   // [5,512]
    const float* bc     = (const float*)d_in[3];   // [5]
    const int*   coords = (const int*)d_in[4];     // [8,512,4]
    const int*   mask   = (const int*)d_in[5];     // [8,512]
    float* out = (float*)d_out;

    token_kernel<<<GRID, THREADS>>>(cl, fuse, Wc, bc, coords, mask, out);
}